// round 2
// baseline (speedup 1.0000x reference)
#include <cuda_runtime.h>

// Sinkhorn OT, n=m=8192, d=64, eps=0.1, 100 iterations.
// Strategy: never materialize K (would be 51 TB of traffic over 201 sweeps).
// Recompute exp(-cdist/eps) on the fly each sweep from L2-resident x,y
// using an fp32 SGEMM-style kernel fused with sqrt/exp2 and the row reduction.

#define NPTS  8192
#define DDIM  64
#define ITERS 100
#define BM    64      // rows per CTA
#define BN    128     // cols per inner tile
#define NTHR  256
#define MARGV (1.0f/8192.0f)
// -log2(e)/eps : exp(-C/eps) = exp2(C * KE)
#define KE    (-14.426950408889634f)

__device__ float g_u[NPTS];
__device__ float g_v[NPTS];
__device__ float g_xsq[NPTS];
__device__ float g_ysq[NPTS];
__device__ float g_xT[DDIM * NPTS];   // x transposed: [k][i]
__device__ float g_yT[DDIM * NPTS];   // y transposed: [k][j]

__device__ __forceinline__ float sqrt_approx(float a) {
    float r; asm("sqrt.approx.f32 %0,%1;" : "=f"(r) : "f"(a)); return r;
}
__device__ __forceinline__ float ex2_approx(float a) {
    float r; asm("ex2.approx.f32 %0,%1;" : "=f"(r) : "f"(a)); return r;
}

// ---------------------------------------------------------------------------
// prep: squared norms of all rows of x and y, and u0 = 1/n
// ---------------------------------------------------------------------------
__global__ void prep_kernel(const float* __restrict__ x,
                            const float* __restrict__ y) {
    int i = blockIdx.x * blockDim.x + threadIdx.x;
    const float4* xr = (const float4*)(x + (size_t)i * DDIM);
    const float4* yr = (const float4*)(y + (size_t)i * DDIM);
    float sx = 0.f, sy = 0.f;
#pragma unroll
    for (int k = 0; k < DDIM / 4; k++) {
        float4 a = xr[k]; sx += a.x*a.x + a.y*a.y + a.z*a.z + a.w*a.w;
        float4 b = yr[k]; sy += b.x*b.x + b.y*b.y + b.z*b.z + b.w*b.w;
    }
    g_xsq[i] = sx;
    g_ysq[i] = sy;
    g_u[i]   = MARGV;
}

// ---------------------------------------------------------------------------
// transpose x,y into [k][point] layout so smem tile fills are coalesced on
// both the global-load side and the smem-store side (no transpose in sweep).
// ---------------------------------------------------------------------------
__global__ void transpose_kernel(const float* __restrict__ x,
                                 const float* __restrict__ y) {
    __shared__ float t[32][33];
    const float* src = blockIdx.z ? y : x;
    float*       dst = blockIdx.z ? g_yT : g_xT;
    int i0 = blockIdx.x * 32;
    int k0 = blockIdx.y * 32;
    int tx = threadIdx.x, ty = threadIdx.y;   // block (32, 8)
#pragma unroll
    for (int p = 0; p < 32; p += 8)
        t[ty + p][tx] = src[(size_t)(i0 + ty + p) * DDIM + k0 + tx];
    __syncthreads();
#pragma unroll
    for (int p = 0; p < 32; p += 8)
        dst[(size_t)(k0 + ty + p) * NPTS + i0 + tx] = t[tx][ty + p];
}

// ---------------------------------------------------------------------------
// sweep: out_i = MARG / sum_j exp(-||A_i - B_j|| / eps) * w_j
// CTA owns BM=64 rows of A and loops over all 8192 cols (B) in BN=128 tiles.
// Thread micro-tile: 4 rows x 8 cols (cols split 4+4 at offset 64 so the
// inner LDS.128 reads have 16B*lane stride -> conflict-free).
// Implemented as a device function; two thin global wrappers bind the
// operands at compile time (no runtime pointer-select overhead).
// ---------------------------------------------------------------------------
__device__ __forceinline__ void sweep_body(
    const float* __restrict__ AT,  const float* __restrict__ Asq,
    const float* __restrict__ BT,  const float* __restrict__ Bsq,
    const float* __restrict__ w,   float* __restrict__ out) {

    __shared__ float As[DDIM][BM];   // 16 KB
    __shared__ float Bs[DDIM][BN];   // 32 KB

    int tid = threadIdx.x;
    int tx  = tid & 15;      // 16 col-groups
    int ty  = tid >> 4;      // 16 row-groups
    int row0 = blockIdx.x * BM;

    // Load A tile (64 k x 64 rows) once; coalesced, linear smem store.
    {
        float4* As4 = (float4*)As;
#pragma unroll
        for (int p = 0; p < 4; p++) {
            int idx = tid + p * NTHR;          // 0..1023 float4s
            int k   = idx >> 4;
            int r4  = idx & 15;
            As4[idx] = ((const float4*)(AT + (size_t)k * NPTS + row0))[r4];
        }
    }

    float asq[4];
#pragma unroll
    for (int r = 0; r < 4; r++) asq[r] = Asq[row0 + ty * 4 + r];

    float rs[4] = {0.f, 0.f, 0.f, 0.f};

    for (int j0 = 0; j0 < NPTS; j0 += BN) {
        __syncthreads();
        {
            float4* Bs4 = (float4*)Bs;
#pragma unroll
            for (int p = 0; p < 8; p++) {
                int idx = tid + p * NTHR;      // 0..2047 float4s
                int k   = idx >> 5;
                int j4  = idx & 31;
                Bs4[idx] = ((const float4*)(BT + (size_t)k * NPTS + j0))[j4];
            }
        }
        __syncthreads();

        float acc[4][8];
#pragma unroll
        for (int r = 0; r < 4; r++)
#pragma unroll
            for (int c = 0; c < 8; c++) acc[r][c] = 0.f;

#pragma unroll 8
        for (int k = 0; k < DDIM; k++) {
            float4 av = *(const float4*)&As[k][ty * 4];
            float4 b0 = *(const float4*)&Bs[k][tx * 4];
            float4 b1 = *(const float4*)&Bs[k][64 + tx * 4];
            float ar[4] = {av.x, av.y, av.z, av.w};
            float bc[8] = {b0.x, b0.y, b0.z, b0.w, b1.x, b1.y, b1.z, b1.w};
#pragma unroll
            for (int r = 0; r < 4; r++)
#pragma unroll
                for (int c = 0; c < 8; c++)
                    acc[r][c] = fmaf(ar[r], bc[c], acc[r][c]);
        }

        // Epilogue: dist -> kernel value -> weighted row partial sums
        float bsqv[8], wv[8];
#pragma unroll
        for (int c = 0; c < 4; c++) {
            int j = j0 + tx * 4 + c;
            bsqv[c] = Bsq[j];  wv[c] = w[j];
            int j2 = j0 + 64 + tx * 4 + c;
            bsqv[4 + c] = Bsq[j2];  wv[4 + c] = w[j2];
        }
#pragma unroll
        for (int r = 0; r < 4; r++) {
            float s = rs[r];
#pragma unroll
            for (int c = 0; c < 8; c++) {
                float sq = fmaf(-2.f, acc[r][c], asq[r] + bsqv[c]);
                sq = fmaxf(sq, 1e-12f);
                float Cd = sqrt_approx(sq);
                s = fmaf(ex2_approx(Cd * KE), wv[c], s);
            }
            rs[r] = s;
        }
    }

    // Reduce the 16 tx lanes of each half-warp (same 4 rows), write out.
#pragma unroll
    for (int r = 0; r < 4; r++) {
        float v = rs[r];
#pragma unroll
        for (int off = 8; off >= 1; off >>= 1)
            v += __shfl_xor_sync(0xffffffffu, v, off);
        if (tx == 0) out[row0 + ty * 4 + r] = MARGV / v;
    }
}

// v = b / (K^T u):  A=y, B=x, w=u, out=v
__global__ __launch_bounds__(NTHR) void sweep0_kernel() {
    sweep_body(g_yT, g_ysq, g_xT, g_xsq, g_u, g_v);
}
// u = a / (K v):    A=x, B=y, w=v, out=u
__global__ __launch_bounds__(NTHR) void sweep1_kernel() {
    sweep_body(g_xT, g_xsq, g_yT, g_ysq, g_v, g_u);
}

// ---------------------------------------------------------------------------
// pi: out[i][j] = u_i * exp(-||x_i - y_j||/eps) * v_j   (256 MB write)
// ---------------------------------------------------------------------------
__global__ __launch_bounds__(NTHR) void pi_kernel(float* __restrict__ out) {
    const float* AT = g_xT;  const float* Asq = g_xsq;
    const float* BT = g_yT;  const float* Bsq = g_ysq;

    __shared__ float As[DDIM][BM];
    __shared__ float Bs[DDIM][BN];

    int tid = threadIdx.x;
    int tx  = tid & 15;
    int ty  = tid >> 4;
    int row0 = blockIdx.x * BM;

    {
        float4* As4 = (float4*)As;
#pragma unroll
        for (int p = 0; p < 4; p++) {
            int idx = tid + p * NTHR;
            int k   = idx >> 4;
            int r4  = idx & 15;
            As4[idx] = ((const float4*)(AT + (size_t)k * NPTS + row0))[r4];
        }
    }

    float asq[4], uu[4];
#pragma unroll
    for (int r = 0; r < 4; r++) {
        asq[r] = Asq[row0 + ty * 4 + r];
        uu[r]  = g_u[row0 + ty * 4 + r];
    }

    for (int j0 = 0; j0 < NPTS; j0 += BN) {
        __syncthreads();
        {
            float4* Bs4 = (float4*)Bs;
#pragma unroll
            for (int p = 0; p < 8; p++) {
                int idx = tid + p * NTHR;
                int k   = idx >> 5;
                int j4  = idx & 31;
                Bs4[idx] = ((const float4*)(BT + (size_t)k * NPTS + j0))[j4];
            }
        }
        __syncthreads();

        float acc[4][8];
#pragma unroll
        for (int r = 0; r < 4; r++)
#pragma unroll
            for (int c = 0; c < 8; c++) acc[r][c] = 0.f;

#pragma unroll 8
        for (int k = 0; k < DDIM; k++) {
            float4 av = *(const float4*)&As[k][ty * 4];
            float4 b0 = *(const float4*)&Bs[k][tx * 4];
            float4 b1 = *(const float4*)&Bs[k][64 + tx * 4];
            float ar[4] = {av.x, av.y, av.z, av.w};
            float bc[8] = {b0.x, b0.y, b0.z, b0.w, b1.x, b1.y, b1.z, b1.w};
#pragma unroll
            for (int r = 0; r < 4; r++)
#pragma unroll
                for (int c = 0; c < 8; c++)
                    acc[r][c] = fmaf(ar[r], bc[c], acc[r][c]);
        }

        float bsqv[8], vv[8];
#pragma unroll
        for (int c = 0; c < 4; c++) {
            int j = j0 + tx * 4 + c;
            bsqv[c] = Bsq[j];  vv[c] = g_v[j];
            int j2 = j0 + 64 + tx * 4 + c;
            bsqv[4 + c] = Bsq[j2];  vv[4 + c] = g_v[j2];
        }
#pragma unroll
        for (int r = 0; r < 4; r++) {
            float o[8];
#pragma unroll
            for (int c = 0; c < 8; c++) {
                float sq = fmaf(-2.f, acc[r][c], asq[r] + bsqv[c]);
                sq = fmaxf(sq, 1e-12f);
                float Cd = sqrt_approx(sq);
                o[c] = uu[r] * ex2_approx(Cd * KE) * vv[c];
            }
            size_t base = (size_t)(row0 + ty * 4 + r) * NPTS + j0;
            float4 s0 = make_float4(o[0], o[1], o[2], o[3]);
            float4 s1 = make_float4(o[4], o[5], o[6], o[7]);
            *(float4*)&out[base + tx * 4]      = s0;
            *(float4*)&out[base + 64 + tx * 4] = s1;
        }
    }
}

// ---------------------------------------------------------------------------
extern "C" void kernel_launch(void* const* d_in, const int* in_sizes, int n_in,
                              void* d_out, int out_size) {
    const float* x = (const float*)d_in[0];
    const float* y = (const float*)d_in[1];
    (void)in_sizes; (void)n_in; (void)out_size;

    prep_kernel<<<NPTS / NTHR, NTHR>>>(x, y);
    transpose_kernel<<<dim3(NPTS / 32, DDIM / 32, 2), dim3(32, 8)>>>(x, y);

    for (int it = 0; it < ITERS; it++) {
        sweep0_kernel<<<NPTS / BM, NTHR>>>();   // v = b / (K^T u)
        sweep1_kernel<<<NPTS / BM, NTHR>>>();   // u = a / (K  v)
    }
    sweep0_kernel<<<NPTS / BM, NTHR>>>();       // final v
    pi_kernel<<<NPTS / BM, NTHR>>>((float*)d_out);
}

// round 3
// speedup vs baseline: 1.3634x; 1.3634x over previous
#include <cuda_runtime.h>

// Sinkhorn OT, n=m=8192, d=64, eps=0.1, 100 iterations.
// K = exp(-cdist/eps) recomputed on the fly each sweep (materializing K would
// be 51 TB of HBM traffic). R3: fill all 148 SMs (grid 512 via 4-way j-split
// with partial sums + tiny finalize) and 8x8 micro-tiles so the LDS crossbar
// (128 B/cyc/SM) no longer caps the FMA pipe.

#define NPTS   8192
#define DDIM   64
#define ITERS  100
#define BM     64      // rows per CTA
#define BN     128     // cols per inner tile
#define NTHR   128     // 8x8 micro-tile: 16 col-groups x 8 row-groups
#define NSPLIT 4
#define JCHUNK (NPTS / NSPLIT)      // 2048
#define MARGV  (1.0f/8192.0f)
// -log2(e)/eps : exp(-C/eps) = exp2(C * KE)
#define KE     (-14.426950408889634f)

__device__ float g_u[NPTS];
__device__ float g_v[NPTS];
__device__ float g_xsq[NPTS];
__device__ float g_ysq[NPTS];
__device__ float g_xT[DDIM * NPTS];     // x transposed: [k][i]
__device__ float g_yT[DDIM * NPTS];     // y transposed: [k][j]
__device__ float g_part[NSPLIT * NPTS]; // per-chunk partial row sums

__device__ __forceinline__ float sqrt_approx(float a) {
    float r; asm("sqrt.approx.f32 %0,%1;" : "=f"(r) : "f"(a)); return r;
}
__device__ __forceinline__ float ex2_approx(float a) {
    float r; asm("ex2.approx.f32 %0,%1;" : "=f"(r) : "f"(a)); return r;
}

// ---------------------------------------------------------------------------
// prep: squared norms of all rows of x and y, and u0 = 1/n
// ---------------------------------------------------------------------------
__global__ void prep_kernel(const float* __restrict__ x,
                            const float* __restrict__ y) {
    int i = blockIdx.x * blockDim.x + threadIdx.x;
    const float4* xr = (const float4*)(x + (size_t)i * DDIM);
    const float4* yr = (const float4*)(y + (size_t)i * DDIM);
    float sx = 0.f, sy = 0.f;
#pragma unroll
    for (int k = 0; k < DDIM / 4; k++) {
        float4 a = xr[k]; sx += a.x*a.x + a.y*a.y + a.z*a.z + a.w*a.w;
        float4 b = yr[k]; sy += b.x*b.x + b.y*b.y + b.z*b.z + b.w*b.w;
    }
    g_xsq[i] = sx;
    g_ysq[i] = sy;
    g_u[i]   = MARGV;
}

// ---------------------------------------------------------------------------
// transpose x,y into [k][point] layout (one-time)
// ---------------------------------------------------------------------------
__global__ void transpose_kernel(const float* __restrict__ x,
                                 const float* __restrict__ y) {
    __shared__ float t[32][33];
    const float* src = blockIdx.z ? y : x;
    float*       dst = blockIdx.z ? g_yT : g_xT;
    int i0 = blockIdx.x * 32;
    int k0 = blockIdx.y * 32;
    int tx = threadIdx.x, ty = threadIdx.y;   // block (32, 8)
#pragma unroll
    for (int p = 0; p < 32; p += 8)
        t[ty + p][tx] = src[(size_t)(i0 + ty + p) * DDIM + k0 + tx];
    __syncthreads();
#pragma unroll
    for (int p = 0; p < 32; p += 8)
        dst[(size_t)(k0 + ty + p) * NPTS + i0 + tx] = t[tx][ty + p];
}

// ---------------------------------------------------------------------------
// sweep: g_part[chunk][i] = sum_{j in chunk} exp(-||A_i - B_j||/eps) * w_j
// CTA: BM=64 rows x one JCHUNK=2048 j-range (16 tiles of BN=128).
// Thread micro-tile 8 rows x 8 cols (cols split 4+4 at offset 64 so inner
// LDS.128 reads are conflict-free).
// ---------------------------------------------------------------------------
__device__ __forceinline__ void sweep_body(
    const float* __restrict__ AT,  const float* __restrict__ Asq,
    const float* __restrict__ BT,  const float* __restrict__ Bsq,
    const float* __restrict__ w) {

    __shared__ float As[DDIM][BM];   // 16 KB
    __shared__ float Bs[DDIM][BN];   // 32 KB

    int tid = threadIdx.x;
    int tx  = tid & 15;      // 16 col-groups (x4 +split4 = 8 cols)
    int ty  = tid >> 4;      // 8 row-groups  (x8 rows)
    int row0  = blockIdx.x * BM;
    int jbase = blockIdx.y * JCHUNK;

    // A tile fill: 1024 float4, coalesced, linear smem store.
    {
        float4* As4 = (float4*)As;
#pragma unroll
        for (int p = 0; p < 8; p++) {
            int idx = tid + p * NTHR;
            int k   = idx >> 4;
            int r4  = idx & 15;
            As4[idx] = ((const float4*)(AT + (size_t)k * NPTS + row0))[r4];
        }
    }

    float asq[8];
#pragma unroll
    for (int r = 0; r < 8; r++) asq[r] = Asq[row0 + ty * 8 + r];

    float rs[8];
#pragma unroll
    for (int r = 0; r < 8; r++) rs[r] = 0.f;

    for (int jt = 0; jt < JCHUNK; jt += BN) {
        int j0 = jbase + jt;
        __syncthreads();
        {
            float4* Bs4 = (float4*)Bs;
#pragma unroll
            for (int p = 0; p < 16; p++) {
                int idx = tid + p * NTHR;
                int k   = idx >> 5;
                int j4  = idx & 31;
                Bs4[idx] = ((const float4*)(BT + (size_t)k * NPTS + j0))[j4];
            }
        }
        __syncthreads();

        float acc[8][8];
#pragma unroll
        for (int r = 0; r < 8; r++)
#pragma unroll
            for (int c = 0; c < 8; c++) acc[r][c] = 0.f;

#pragma unroll 8
        for (int k = 0; k < DDIM; k++) {
            float4 a0 = *(const float4*)&As[k][ty * 8];
            float4 a1 = *(const float4*)&As[k][ty * 8 + 4];
            float4 b0 = *(const float4*)&Bs[k][tx * 4];
            float4 b1 = *(const float4*)&Bs[k][64 + tx * 4];
            float ar[8] = {a0.x, a0.y, a0.z, a0.w, a1.x, a1.y, a1.z, a1.w};
            float bc[8] = {b0.x, b0.y, b0.z, b0.w, b1.x, b1.y, b1.z, b1.w};
#pragma unroll
            for (int r = 0; r < 8; r++)
#pragma unroll
                for (int c = 0; c < 8; c++)
                    acc[r][c] = fmaf(ar[r], bc[c], acc[r][c]);
        }

        // Epilogue: dist -> kernel -> weighted partial row sums
        float bsqv[8], wv[8];
#pragma unroll
        for (int c = 0; c < 4; c++) {
            int j  = j0 + tx * 4 + c;
            int j2 = j0 + 64 + tx * 4 + c;
            bsqv[c]     = Bsq[j];   wv[c]     = w[j];
            bsqv[4 + c] = Bsq[j2];  wv[4 + c] = w[j2];
        }
#pragma unroll
        for (int r = 0; r < 8; r++) {
            float s = rs[r];
#pragma unroll
            for (int c = 0; c < 8; c++) {
                float sq = fmaf(-2.f, acc[r][c], asq[r] + bsqv[c]);
                sq = fmaxf(sq, 1e-12f);
                float Cd = sqrt_approx(sq);
                s = fmaf(ex2_approx(Cd * KE), wv[c], s);
            }
            rs[r] = s;
        }
    }

    // Reduce the 16 tx lanes (same rows), write partial sums.
#pragma unroll
    for (int r = 0; r < 8; r++) {
        float v = rs[r];
#pragma unroll
        for (int off = 8; off >= 1; off >>= 1)
            v += __shfl_xor_sync(0xffffffffu, v, off);
        if (tx == 0)
            g_part[blockIdx.y * NPTS + row0 + ty * 8 + r] = v;
    }
}

// v-direction partials: A=y, B=x, w=u
__global__ __launch_bounds__(NTHR, 4) void sweep0_kernel() {
    sweep_body(g_yT, g_ysq, g_xT, g_xsq, g_u);
}
// u-direction partials: A=x, B=y, w=v
__global__ __launch_bounds__(NTHR, 4) void sweep1_kernel() {
    sweep_body(g_xT, g_xsq, g_yT, g_ysq, g_v);
}

// finalize: out[i] = MARGV / sum_chunks part[chunk][i];  which: 0 -> g_v, 1 -> g_u
__global__ void finalize_kernel(int which) {
    int i = blockIdx.x * blockDim.x + threadIdx.x;
    float s = 0.f;
#pragma unroll
    for (int c = 0; c < NSPLIT; c++) s += g_part[c * NPTS + i];
    float o = MARGV / s;
    if (which) g_u[i] = o; else g_v[i] = o;
}

// ---------------------------------------------------------------------------
// pi: out[i][j] = u_i * exp(-||x_i - y_j||/eps) * v_j   (256 MB write)
// Same tiling; j-split just partitions the output columns.
// ---------------------------------------------------------------------------
__global__ __launch_bounds__(NTHR, 4) void pi_kernel(float* __restrict__ out) {
    const float* AT = g_xT;  const float* Asq = g_xsq;
    const float* BT = g_yT;  const float* Bsq = g_ysq;

    __shared__ float As[DDIM][BM];
    __shared__ float Bs[DDIM][BN];

    int tid = threadIdx.x;
    int tx  = tid & 15;
    int ty  = tid >> 4;
    int row0  = blockIdx.x * BM;
    int jbase = blockIdx.y * JCHUNK;

    {
        float4* As4 = (float4*)As;
#pragma unroll
        for (int p = 0; p < 8; p++) {
            int idx = tid + p * NTHR;
            int k   = idx >> 4;
            int r4  = idx & 15;
            As4[idx] = ((const float4*)(AT + (size_t)k * NPTS + row0))[r4];
        }
    }

    float asq[8], uu[8];
#pragma unroll
    for (int r = 0; r < 8; r++) {
        asq[r] = Asq[row0 + ty * 8 + r];
        uu[r]  = g_u[row0 + ty * 8 + r];
    }

    for (int jt = 0; jt < JCHUNK; jt += BN) {
        int j0 = jbase + jt;
        __syncthreads();
        {
            float4* Bs4 = (float4*)Bs;
#pragma unroll
            for (int p = 0; p < 16; p++) {
                int idx = tid + p * NTHR;
                int k   = idx >> 5;
                int j4  = idx & 31;
                Bs4[idx] = ((const float4*)(BT + (size_t)k * NPTS + j0))[j4];
            }
        }
        __syncthreads();

        float acc[8][8];
#pragma unroll
        for (int r = 0; r < 8; r++)
#pragma unroll
            for (int c = 0; c < 8; c++) acc[r][c] = 0.f;

#pragma unroll 8
        for (int k = 0; k < DDIM; k++) {
            float4 a0 = *(const float4*)&As[k][ty * 8];
            float4 a1 = *(const float4*)&As[k][ty * 8 + 4];
            float4 b0 = *(const float4*)&Bs[k][tx * 4];
            float4 b1 = *(const float4*)&Bs[k][64 + tx * 4];
            float ar[8] = {a0.x, a0.y, a0.z, a0.w, a1.x, a1.y, a1.z, a1.w};
            float bc[8] = {b0.x, b0.y, b0.z, b0.w, b1.x, b1.y, b1.z, b1.w};
#pragma unroll
            for (int r = 0; r < 8; r++)
#pragma unroll
                for (int c = 0; c < 8; c++)
                    acc[r][c] = fmaf(ar[r], bc[c], acc[r][c]);
        }

        float bsqv[8], vv[8];
#pragma unroll
        for (int c = 0; c < 4; c++) {
            int j  = j0 + tx * 4 + c;
            int j2 = j0 + 64 + tx * 4 + c;
            bsqv[c]     = Bsq[j];   vv[c]     = g_v[j];
            bsqv[4 + c] = Bsq[j2];  vv[4 + c] = g_v[j2];
        }
#pragma unroll
        for (int r = 0; r < 8; r++) {
            float o[8];
#pragma unroll
            for (int c = 0; c < 8; c++) {
                float sq = fmaf(-2.f, acc[r][c], asq[r] + bsqv[c]);
                sq = fmaxf(sq, 1e-12f);
                float Cd = sqrt_approx(sq);
                o[c] = uu[r] * ex2_approx(Cd * KE) * vv[c];
            }
            size_t base = (size_t)(row0 + ty * 8 + r) * NPTS + j0;
            *(float4*)&out[base + tx * 4]      = make_float4(o[0], o[1], o[2], o[3]);
            *(float4*)&out[base + 64 + tx * 4] = make_float4(o[4], o[5], o[6], o[7]);
        }
    }
}

// ---------------------------------------------------------------------------
extern "C" void kernel_launch(void* const* d_in, const int* in_sizes, int n_in,
                              void* d_out, int out_size) {
    const float* x = (const float*)d_in[0];
    const float* y = (const float*)d_in[1];
    (void)in_sizes; (void)n_in; (void)out_size;

    prep_kernel<<<NPTS / 256, 256>>>(x, y);
    transpose_kernel<<<dim3(NPTS / 32, DDIM / 32, 2), dim3(32, 8)>>>(x, y);

    dim3 sgrid(NPTS / BM, NSPLIT);
    for (int it = 0; it < ITERS; it++) {
        sweep0_kernel<<<sgrid, NTHR>>>();          // partials of K^T u
        finalize_kernel<<<NPTS / 256, 256>>>(0);   // v = b / (K^T u)
        sweep1_kernel<<<sgrid, NTHR>>>();          // partials of K v
        finalize_kernel<<<NPTS / 256, 256>>>(1);   // u = a / (K v)
    }
    sweep0_kernel<<<sgrid, NTHR>>>();              // final v
    finalize_kernel<<<NPTS / 256, 256>>>(0);
    pi_kernel<<<sgrid, NTHR>>>((float*)d_out);
}